// round 1
// baseline (speedup 1.0000x reference)
#include <cuda_runtime.h>
#include <cuda_bf16.h>
#include <cstdint>

// Problem constants
#define BB 16
#define SS 64
#define NNODE 128
#define FF 16
#define HH 64
#define EE 1024
#define ET 1152      // E + N self loops
#define LL 2
#define WS 65        // padded weight stride in smem

// ---------------- device scratch ----------------
__device__ float g_h[(size_t)BB * NNODE * SS * HH];   // [B,N,S,H] seqs layout
__device__ float g_hlast[(size_t)BB * NNODE * HH];
__device__ int   g_csr_off[NNODE + 1];
__device__ int   g_csr_src[ET];
__device__ int   g_csr_tgt[ET];

// ---------------- CSR prep (deterministic, no atomics) ----------------
__global__ void prep_kernel(const int* __restrict__ ei) {
    __shared__ int eis[2 * EE];
    __shared__ int cnt[NNODE];
    __shared__ int off[NNODE + 1];
    int t = threadIdx.x;  // 128 threads
    for (int i = t; i < 2 * EE; i += 128) eis[i] = ei[i];
    __syncthreads();
    int c = 0;
    for (int e = 0; e < ET; e++) {
        int tg = (e < EE) ? eis[EE + e] : (e - EE);
        if (tg == t) c++;
    }
    cnt[t] = c;
    __syncthreads();
    if (t == 0) {
        int sum = 0;
        for (int n = 0; n < NNODE; n++) { off[n] = sum; sum += cnt[n]; }
        off[NNODE] = sum;
    }
    __syncthreads();
    g_csr_off[t] = off[t];
    if (t == 0) g_csr_off[NNODE] = off[NNODE];
    int pos = off[t];
    for (int e = 0; e < ET; e++) {
        int sr = (e < EE) ? eis[e] : (e - EE);
        int tg = (e < EE) ? eis[EE + e] : (e - EE);
        if (tg == t) { g_csr_src[pos] = sr; g_csr_tgt[pos] = tg; pos++; }
    }
}

// ---------------- GNN kernel: one CTA per (b,s) slice ----------------
// smem layout (floats):
//  hbuf 8192 | xl 8192 | xr 8192 | wA 4160 | wB 4160 | ea 1152 | atts 64
//  then ints: soff 132 | ssrc 1152 | stgt 1152
#define GNN_SMEM_FLOATS (8192*3 + 4160*2 + 1152 + 64)
#define GNN_SMEM_BYTES  ((GNN_SMEM_FLOATS + 132 + 1152 + 1152) * 4)

__global__ void __launch_bounds__(256, 1) gnn_kernel(
    const float* __restrict__ x,
    const float* __restrict__ inW, const float* __restrict__ inb,
    const float* __restrict__ Wl, const float* __restrict__ bl,
    const float* __restrict__ Wr, const float* __restrict__ br,
    const float* __restrict__ att, const float* __restrict__ bo)
{
    extern __shared__ float sm[];
    float* hbuf = sm;
    float* xl   = sm + 8192;
    float* xr   = sm + 16384;
    float* wA   = sm + 24576;
    float* wB   = wA + 4160;
    float* ea   = wB + 4160;
    float* atts = ea + 1152;
    int* soff   = (int*)(atts + 64);
    int* ssrc   = soff + 132;
    int* stgt   = ssrc + 1152;

    const int t   = threadIdx.x;
    const int blk = blockIdx.x;
    const int b   = blk >> 6;     // /S
    const int s   = blk & 63;

    // stage CSR + input weights (transposed) + x slice
    for (int i = t; i <= NNODE; i += 256) soff[i] = g_csr_off[i];
    for (int i = t; i < ET; i += 256) { ssrc[i] = g_csr_src[i]; stgt[i] = g_csr_tgt[i]; }
    for (int i = t; i < HH * FF; i += 256) {
        int hh = i >> 4, f = i & 15;               // inW is [H,F]
        wA[f * WS + hh] = inW[i];
    }
    const float* xsl = x + (size_t)blk * NNODE * FF;
    for (int i = t; i < NNODE * FF; i += 256) xl[i] = xsl[i];   // stage x into xl
    __syncthreads();

    const int hh = t & 63;
    const int ng = t >> 6;
    const int lane = t & 31;
    const int wid  = t >> 5;

    // ---- input projection: hbuf = x @ inW^T + inb ----
    {
        float acc[32];
        float bia = inb[hh];
#pragma unroll
        for (int i = 0; i < 32; i++) acc[i] = bia;
#pragma unroll
        for (int k4 = 0; k4 < 4; k4++) {
            float w0 = wA[(4 * k4 + 0) * WS + hh];
            float w1 = wA[(4 * k4 + 1) * WS + hh];
            float w2 = wA[(4 * k4 + 2) * WS + hh];
            float w3 = wA[(4 * k4 + 3) * WS + hh];
#pragma unroll
            for (int i = 0; i < 32; i++) {
                int n = ng + 4 * i;
                float4 v = *(const float4*)&xl[n * FF + 4 * k4];
                acc[i] = fmaf(v.x, w0, acc[i]);
                acc[i] = fmaf(v.y, w1, acc[i]);
                acc[i] = fmaf(v.z, w2, acc[i]);
                acc[i] = fmaf(v.w, w3, acc[i]);
            }
        }
#pragma unroll
        for (int i = 0; i < 32; i++) hbuf[(ng + 4 * i) * HH + hh] = acc[i];
    }
    __syncthreads();

    // ---- GAT layers ----
    for (int l = 0; l < LL; l++) {
        const float* wlp = Wl + l * HH * HH;
        const float* wrp = Wr + l * HH * HH;
        for (int i = t; i < HH * HH; i += 256) {
            int j = i >> 6, k = i & 63;
            wA[k * WS + j] = wlp[i];
            wB[k * WS + j] = wrp[i];
        }
        if (t < HH) atts[t] = att[l * HH + t];
        __syncthreads();

        // xl = hbuf@Wl^T + bl ; xr = hbuf@Wr^T + br
        {
            float blv = bl[l * HH + hh];
            float brv = br[l * HH + hh];
            float accl[32], accr[32];
#pragma unroll
            for (int i = 0; i < 32; i++) { accl[i] = blv; accr[i] = brv; }
#pragma unroll
            for (int k4 = 0; k4 < 16; k4++) {
                float wl0 = wA[(4 * k4 + 0) * WS + hh];
                float wl1 = wA[(4 * k4 + 1) * WS + hh];
                float wl2 = wA[(4 * k4 + 2) * WS + hh];
                float wl3 = wA[(4 * k4 + 3) * WS + hh];
                float wr0 = wB[(4 * k4 + 0) * WS + hh];
                float wr1 = wB[(4 * k4 + 1) * WS + hh];
                float wr2 = wB[(4 * k4 + 2) * WS + hh];
                float wr3 = wB[(4 * k4 + 3) * WS + hh];
#pragma unroll
                for (int i = 0; i < 32; i++) {
                    int n = ng + 4 * i;
                    float4 v = *(const float4*)&hbuf[n * HH + 4 * k4];
                    accl[i] = fmaf(v.x, wl0, accl[i]);
                    accl[i] = fmaf(v.y, wl1, accl[i]);
                    accl[i] = fmaf(v.z, wl2, accl[i]);
                    accl[i] = fmaf(v.w, wl3, accl[i]);
                    accr[i] = fmaf(v.x, wr0, accr[i]);
                    accr[i] = fmaf(v.y, wr1, accr[i]);
                    accr[i] = fmaf(v.z, wr2, accr[i]);
                    accr[i] = fmaf(v.w, wr3, accr[i]);
                }
            }
#pragma unroll
            for (int i = 0; i < 32; i++) {
                int n = ng + 4 * i;
                xl[n * HH + hh] = accl[i];
                xr[n * HH + hh] = accr[i];
            }
        }
        __syncthreads();

        // edge attention scores: a[e] = sum_h leaky(xl[src]+xr[tgt]) * att
        for (int e = wid; e < ET; e += 8) {
            int sr = ssrc[e], tg = stgt[e];
            float v1 = xl[sr * HH + lane]      + xr[tg * HH + lane];
            float v2 = xl[sr * HH + 32 + lane] + xr[tg * HH + 32 + lane];
            v1 = fmaxf(v1, 0.f) + 0.2f * fminf(v1, 0.f);
            v2 = fmaxf(v2, 0.f) + 0.2f * fminf(v2, 0.f);
            float sum = v1 * atts[lane] + v2 * atts[lane + 32];
#pragma unroll
            for (int o = 16; o; o >>= 1) sum += __shfl_xor_sync(0xffffffffu, sum, o);
            if (lane == 0) ea[e] = sum;
        }
        __syncthreads();

        // segment softmax + aggregation per target node
        {
            float bo0 = bo[l * HH + lane];
            float bo1 = bo[l * HH + 32 + lane];
            for (int n = wid; n < NNODE; n += 8) {
                int beg = soff[n], end = soff[n + 1];
                float m = -1e30f;
                for (int i = beg + lane; i < end; i += 32) m = fmaxf(m, ea[i]);
#pragma unroll
                for (int o = 16; o; o >>= 1) m = fmaxf(m, __shfl_xor_sync(0xffffffffu, m, o));
                float z = 0.f;
                for (int i = beg + lane; i < end; i += 32) {
                    float p = __expf(ea[i] - m);
                    ea[i] = p;
                    z += p;
                }
#pragma unroll
                for (int o = 16; o; o >>= 1) z += __shfl_xor_sync(0xffffffffu, z, o);
                float inv = 1.f / z;
                float a0 = 0.f, a1 = 0.f;
                for (int i = beg; i < end; i++) {
                    float al = ea[i] * inv;       // broadcast
                    int sr = ssrc[i];
                    a0 = fmaf(al, xl[sr * HH + lane], a0);
                    a1 = fmaf(al, xl[sr * HH + 32 + lane], a1);
                }
                a0 = fmaxf(a0 + bo0, 0.f);
                a1 = fmaxf(a1 + bo1, 0.f);
                hbuf[n * HH + lane] = a0;
                hbuf[n * HH + 32 + lane] = a1;
            }
        }
        __syncthreads();
    }

    // ---- write to g_h in [B,N,S,H] layout ----
    float4* gh4 = (float4*)g_h;
    for (int q = t; q < NNODE * (HH / 4); q += 256) {
        int n = q >> 4, v = q & 15;
        float4 val = *(const float4*)&hbuf[n * HH + 4 * v];
        gh4[((size_t)(b * NNODE + n) * SS + s) * (HH / 4) + v] = val;
    }
}

// ---------------- GRU kernel: warp handles 2 rows through all 64 steps ----------------
#define GRU_SMEM_BYTES ((12288 * 2 + 512 + 512) * 4)

__global__ void __launch_bounds__(128, 2) gru_kernel(
    const float* __restrict__ Wih, const float* __restrict__ Whh,
    const float* __restrict__ bih, const float* __restrict__ bhh)
{
    extern __shared__ float sm[];
    float* WihT = sm;            // [64][192]
    float* WhhT = sm + 12288;    // [64][192]
    float* xw   = sm + 24576;    // 4 warps * 2 rows * 64
    float* hw   = xw + 512;

    const int t = threadIdx.x, lane = t & 31, wid = t >> 5;
    for (int i = t; i < 192 * 64; i += 128) {
        int j = i >> 6, k = i & 63;
        WihT[k * 192 + j] = Wih[i];
        WhhT[k * 192 + j] = Whh[i];
    }
    for (int i = t; i < 512; i += 128) hw[i] = 0.f;
    __syncthreads();

    const int row0 = (blockIdx.x * 4 + wid) * 2;
    float* xr_ = xw + wid * 128;
    float* hr_ = hw + wid * 128;

    float brz[4], binr[2], bhnr[2];
#pragma unroll
    for (int m = 0; m < 4; m++) brz[m] = bih[lane + 32 * m] + bhh[lane + 32 * m];
#pragma unroll
    for (int m = 0; m < 2; m++) {
        binr[m] = bih[128 + lane + 32 * m];
        bhnr[m] = bhh[128 + lane + 32 * m];
    }

    for (int s = 0; s < SS; s++) {
        // stage xt for 2 rows (coalesced 64-float runs)
#pragma unroll
        for (int q = 0; q < 4; q++) {
            int idx = lane + 32 * q;
            int r = idx >> 6, hh2 = idx & 63;
            xr_[idx] = g_h[((size_t)(row0 + r) * SS + s) * HH + hh2];
        }
        __syncwarp();

        float arz[2][4], ain[2][2], ahn[2][2];
#pragma unroll
        for (int r = 0; r < 2; r++) {
#pragma unroll
            for (int m = 0; m < 4; m++) arz[r][m] = brz[m];
#pragma unroll
            for (int m = 0; m < 2; m++) { ain[r][m] = binr[m]; ahn[r][m] = bhnr[m]; }
        }

#pragma unroll 4
        for (int k = 0; k < HH; k++) {
            const float* wi = &WihT[k * 192 + lane];
            const float* wh = &WhhT[k * 192 + lane];
            float wi0 = wi[0],  wi1 = wi[32],  wi2 = wi[64],  wi3 = wi[96],  wi4 = wi[128], wi5 = wi[160];
            float wh0 = wh[0],  wh1 = wh[32],  wh2 = wh[64],  wh3 = wh[96],  wh4 = wh[128], wh5 = wh[160];
#pragma unroll
            for (int r = 0; r < 2; r++) {
                float xk = xr_[r * 64 + k];
                float hk = hr_[r * 64 + k];
                arz[r][0] = fmaf(hk, wh0, fmaf(xk, wi0, arz[r][0]));
                arz[r][1] = fmaf(hk, wh1, fmaf(xk, wi1, arz[r][1]));
                arz[r][2] = fmaf(hk, wh2, fmaf(xk, wi2, arz[r][2]));
                arz[r][3] = fmaf(hk, wh3, fmaf(xk, wi3, arz[r][3]));
                ain[r][0] = fmaf(xk, wi4, ain[r][0]);
                ain[r][1] = fmaf(xk, wi5, ain[r][1]);
                ahn[r][0] = fmaf(hk, wh4, ahn[r][0]);
                ahn[r][1] = fmaf(hk, wh5, ahn[r][1]);
            }
        }

#pragma unroll
        for (int r = 0; r < 2; r++) {
            float rg0 = 1.f / (1.f + __expf(-arz[r][0]));
            float rg1 = 1.f / (1.f + __expf(-arz[r][1]));
            float zg0 = 1.f / (1.f + __expf(-arz[r][2]));
            float zg1 = 1.f / (1.f + __expf(-arz[r][3]));
            float nx0 = ain[r][0] + rg0 * ahn[r][0];
            float nx1 = ain[r][1] + rg1 * ahn[r][1];
            nx0 = fminf(fmaxf(nx0, -15.f), 15.f);
            nx1 = fminf(fmaxf(nx1, -15.f), 15.f);
            float e0 = __expf(2.f * nx0), e1 = __expf(2.f * nx1);
            float n0 = (e0 - 1.f) / (e0 + 1.f);
            float n1 = (e1 - 1.f) / (e1 + 1.f);
            float h0 = hr_[r * 64 + lane];
            float h1 = hr_[r * 64 + 32 + lane];
            h0 = n0 + zg0 * (h0 - n0);   // (1-z)*n + z*h
            h1 = n1 + zg1 * (h1 - n1);
            hr_[r * 64 + lane] = h0;
            hr_[r * 64 + 32 + lane] = h1;
        }
        __syncwarp();
    }

#pragma unroll
    for (int r = 0; r < 2; r++) {
        g_hlast[(size_t)(row0 + r) * HH + lane]      = hr_[r * 64 + lane];
        g_hlast[(size_t)(row0 + r) * HH + 32 + lane] = hr_[r * 64 + 32 + lane];
    }
}

// ---------------- output heads: warp per row ----------------
__global__ void __launch_bounds__(256) heads_kernel(
    const float* __restrict__ oW1, const float* __restrict__ ob1,
    const float* __restrict__ oW2, const float* __restrict__ ob2,
    const float* __restrict__ dW1, const float* __restrict__ db1,
    const float* __restrict__ dW2, const float* __restrict__ db2,
    float* __restrict__ out)
{
    __shared__ float oW1T[64 * 32], dW1T[64 * 32];
    __shared__ float oW2s[32], dW2s[32], ob1s[32], db1s[32];
    __shared__ float ob2s, db2s;
    const int t = threadIdx.x, lane = t & 31, wid = t >> 5;
    for (int i = t; i < 32 * 64; i += 256) {
        int j = i >> 6, k = i & 63;       // W1 is [32,64]
        oW1T[k * 32 + j] = oW1[i];
        dW1T[k * 32 + j] = dW1[i];
    }
    if (t < 32) { oW2s[t] = oW2[t]; dW2s[t] = dW2[t]; ob1s[t] = ob1[t]; db1s[t] = db1[t]; }
    if (t == 0) { ob2s = ob2[0]; db2s = db2[0]; }
    __syncthreads();

    const int nwarps = gridDim.x * 8;
    for (int row = blockIdx.x * 8 + wid; row < BB * NNODE; row += nwarps) {
        float h0 = g_hlast[(size_t)row * HH + lane];
        float h1 = g_hlast[(size_t)row * HH + 32 + lane];
        float aO = ob1s[lane];
        float aD = db1s[lane];
#pragma unroll 8
        for (int k = 0; k < HH; k++) {
            float src = (k < 32) ? h0 : h1;
            float hk = __shfl_sync(0xffffffffu, src, k & 31);
            aO = fmaf(hk, oW1T[k * 32 + lane], aO);
            aD = fmaf(hk, dW1T[k * 32 + lane], aD);
        }
        aO = fmaxf(aO, 0.f) * oW2s[lane];
        aD = fmaxf(aD, 0.f) * dW2s[lane];
#pragma unroll
        for (int o = 16; o; o >>= 1) {
            aO += __shfl_xor_sync(0xffffffffu, aO, o);
            aD += __shfl_xor_sync(0xffffffffu, aD, o);
        }
        if (lane == 0) {
            out[row] = aO + ob2s;                 // order  [B,N]
            out[BB * NNODE + row] = aD + db2s;    // demand [B,N]
        }
    }
}

// ---------------- launch ----------------
extern "C" void kernel_launch(void* const* d_in, const int* in_sizes, int n_in,
                              void* d_out, int out_size) {
    const float* x    = (const float*)d_in[0];
    const int*   ei   = (const int*)  d_in[1];
    const float* inW  = (const float*)d_in[2];
    const float* inb  = (const float*)d_in[3];
    const float* gWl  = (const float*)d_in[4];
    const float* gbl  = (const float*)d_in[5];
    const float* gWr  = (const float*)d_in[6];
    const float* gbr  = (const float*)d_in[7];
    const float* gatt = (const float*)d_in[8];
    const float* gbo  = (const float*)d_in[9];
    const float* Wih  = (const float*)d_in[10];
    const float* Whh  = (const float*)d_in[11];
    const float* bih  = (const float*)d_in[12];
    const float* bhh  = (const float*)d_in[13];
    const float* oW1  = (const float*)d_in[14];
    const float* ob1  = (const float*)d_in[15];
    const float* oW2  = (const float*)d_in[16];
    const float* ob2  = (const float*)d_in[17];
    const float* dW1  = (const float*)d_in[18];
    const float* db1  = (const float*)d_in[19];
    const float* dW2  = (const float*)d_in[20];
    const float* db2  = (const float*)d_in[21];

    cudaFuncSetAttribute(gnn_kernel, cudaFuncAttributeMaxDynamicSharedMemorySize, GNN_SMEM_BYTES);
    cudaFuncSetAttribute(gru_kernel, cudaFuncAttributeMaxDynamicSharedMemorySize, GRU_SMEM_BYTES);

    prep_kernel<<<1, 128>>>(ei);
    gnn_kernel<<<BB * SS, 256, GNN_SMEM_BYTES>>>(x, inW, inb, gWl, gbl, gWr, gbr, gatt, gbo);
    gru_kernel<<<(BB * NNODE) / 8, 128, GRU_SMEM_BYTES>>>(Wih, Whh, bih, bhh);
    heads_kernel<<<64, 256>>>(oW1, ob1, oW2, ob2, dW1, db1, dW2, db2, (float*)d_out);
}